// round 1
// baseline (speedup 1.0000x reference)
#include <cuda_runtime.h>
#include <math.h>

#define NN 100000
#define EE 3200000
#define DD 64
#define NBCOLS 384
#define CHUNK 6400000

// ---------------- static device scratch (no allocs allowed) ----------------
__device__ float g_XM[(size_t)NN * NBCOLS];   // [N, 6*D] concat buffer (153.6 MB)
__device__ float g_h1[(size_t)NN * DD];       // x @ W1
__device__ float g_h2[(size_t)NN * DD];       // layer-2 h per graph
__device__ float g_deg[NN];
__device__ float g_dinv[NN];
__device__ int   g_cnt[NN + 1];               // histogram -> col_ptr (CSC)
__device__ int   g_cursor[NN];
__device__ int2  g_csc[EE];                   // {src, __float_as_int(norm)}
__device__ float g_csum[8];
__device__ float g_coef[8];                   // sigmoid(att)*conv_w

// ---------------- per-graph CSC build ----------------
__global__ void k_zero_graph() {
    int i = blockIdx.x * blockDim.x + threadIdx.x;
    if (i < NN) { g_deg[i] = 0.0f; g_cnt[i] = 0; }
}

__global__ void k_deg_hist(const int* __restrict__ col, const float* __restrict__ w) {
    int e = blockIdx.x * blockDim.x + threadIdx.x;
    if (e >= EE) return;
    int c = col[e];
    atomicAdd(&g_deg[c], w[e]);
    atomicAdd(&g_cnt[c], 1);
}

__global__ void k_dinv() {
    int i = blockIdx.x * blockDim.x + threadIdx.x;
    if (i < NN) g_dinv[i] = rsqrtf(g_deg[i] + 1.0f);  // deg includes self-loop weight 1
}

// exclusive scan of g_cnt[0..N) -> col_ptr (also copied into cursor). 1 block.
__global__ void k_scan() {
    __shared__ int ps[1024];
    int t = threadIdx.x;
    const int C = 98;  // 1024*98 >= 100000
    int b0 = t * C;
    int b1 = b0 + C; if (b1 > NN) b1 = NN;
    int s = 0;
    if (b0 < NN) for (int i = b0; i < b1; i++) s += g_cnt[i];
    ps[t] = s;
    __syncthreads();
    for (int off = 1; off < 1024; off <<= 1) {
        int v = (t >= off) ? ps[t - off] : 0;
        __syncthreads();
        ps[t] += v;
        __syncthreads();
    }
    int run = ps[t] - s;  // exclusive prefix
    if (b0 < NN) {
        for (int i = b0; i < b1; i++) {
            int v = g_cnt[i];
            g_cnt[i] = run;
            g_cursor[i] = run;
            run += v;
        }
    }
    if (t == 0) g_cnt[NN] = EE;
}

__global__ void k_scatter(const int* __restrict__ row, const int* __restrict__ col,
                          const float* __restrict__ w) {
    int e = blockIdx.x * blockDim.x + threadIdx.x;
    if (e >= EE) return;
    int c = col[e];
    int r = row[e];
    int slot = atomicAdd(&g_cursor[c], 1);
    float nrm = g_dinv[r] * w[e] * g_dinv[c];
    g_csc[slot] = make_int2(r, __float_as_int(nrm));
}

// ---------------- GEMM: H[n,d] = sum_k A[n,k]*Wm[k,d], fp32, tiled ----------------
__global__ void k_gemm(const float* __restrict__ A, int lda,
                       const float* __restrict__ Wm, float* __restrict__ H) {
    __shared__ float sA[64][65];
    __shared__ float sW[64 * 64];
    int n0 = blockIdx.x * 64;
    int t = threadIdx.x;  // 256
    for (int i = t; i < 4096; i += 256) sW[i] = Wm[i];
    for (int i = t; i < 4096; i += 256) {
        int r = i >> 6, c = i & 63;
        int n = n0 + r;
        sA[r][c] = (n < NN) ? A[(size_t)n * lda + c] : 0.0f;
    }
    __syncthreads();
    int d2 = t & 31;   // column pair
    int rg = t >> 5;   // row group: rows rg*8 .. rg*8+7
    float2 acc[8];
#pragma unroll
    for (int i = 0; i < 8; i++) acc[i] = make_float2(0.f, 0.f);
    const float2* sW2 = (const float2*)sW;
#pragma unroll 8
    for (int k = 0; k < 64; k++) {
        float2 wv = sW2[k * 32 + d2];
#pragma unroll
        for (int i = 0; i < 8; i++) {
            float a = sA[rg * 8 + i][k];
            acc[i].x += a * wv.x;
            acc[i].y += a * wv.y;
        }
    }
#pragma unroll
    for (int i = 0; i < 8; i++) {
        int n = n0 + rg * 8 + i;
        if (n < NN) *(float2*)&H[(size_t)n * DD + 2 * d2] = acc[i];
    }
}

// ---------------- aggregate: warp per node, float2 per lane ----------------
__global__ void k_aggregate(const float* __restrict__ H, const float* __restrict__ bias,
                            float* __restrict__ XMout) {
    int wnode = (blockIdx.x * blockDim.x + threadIdx.x) >> 5;
    if (wnode >= NN) return;
    int lane = threadIdx.x & 31;
    int beg = g_cnt[wnode];
    int end = g_cnt[wnode + 1];
    float dj = g_dinv[wnode];
    float sl = dj * dj;
    float2 acc = *(const float2*)&H[(size_t)wnode * DD + 2 * lane];
    acc.x *= sl; acc.y *= sl;  // self-loop contribution
    int e = beg;
    for (; e + 2 <= end; e += 2) {
        int2 e0 = g_csc[e];
        int2 e1 = g_csc[e + 1];
        float2 h0 = *(const float2*)&H[(size_t)e0.x * DD + 2 * lane];
        float2 h1 = *(const float2*)&H[(size_t)e1.x * DD + 2 * lane];
        float n0 = __int_as_float(e0.y);
        float n1 = __int_as_float(e1.y);
        acc.x += n0 * h0.x;  acc.y += n0 * h0.y;
        acc.x += n1 * h1.x;  acc.y += n1 * h1.y;
    }
    if (e < end) {
        int2 e0 = g_csc[e];
        float2 h0 = *(const float2*)&H[(size_t)e0.x * DD + 2 * lane];
        float n0 = __int_as_float(e0.y);
        acc.x += n0 * h0.x;  acc.y += n0 * h0.y;
    }
    float2 bv = *(const float2*)&bias[2 * lane];
    acc.x = fmaxf(acc.x + bv.x, 0.0f);
    acc.y = fmaxf(acc.y + bv.y, 0.0f);
    *(float2*)&XMout[(size_t)wnode * NBCOLS + 2 * lane] = acc;
}

// ---------------- epilogue ----------------
__global__ void k_zero8() { if (threadIdx.x < 8) g_csum[threadIdx.x] = 0.0f; }

__global__ void k_chunksum() {
    int c = blockIdx.y;
    const float4* p = (const float4*)(g_XM + (size_t)c * CHUNK);
    const int tot = CHUNK / 4;
    float s = 0.0f;
    for (int i = blockIdx.x * blockDim.x + threadIdx.x; i < tot; i += gridDim.x * blockDim.x) {
        float4 v = p[i];
        s += (v.x + v.y) + (v.z + v.w);
    }
    for (int o = 16; o; o >>= 1) s += __shfl_down_sync(0xffffffffu, s, o);
    __shared__ float sh[32];
    if ((threadIdx.x & 31) == 0) sh[threadIdx.x >> 5] = s;
    __syncthreads();
    if (threadIdx.x < 32) {
        s = (threadIdx.x < (int)(blockDim.x >> 5)) ? sh[threadIdx.x] : 0.0f;
        for (int o = 16; o; o >>= 1) s += __shfl_down_sync(0xffffffffu, s, o);
        if (threadIdx.x == 0) atomicAdd(&g_csum[c], s);
    }
}

__global__ void k_att(const float* __restrict__ fc1w, const float* __restrict__ fc1b,
                      const float* __restrict__ fc2w, const float* __restrict__ fc2b,
                      const float* __restrict__ convw) {
    __shared__ float m[6], a1[30];
    int t = threadIdx.x;
    if (t < 6) m[t] = g_csum[t] * (1.0f / (float)CHUNK);
    __syncthreads();
    if (t < 30) {
        float s = fc1b[t];
        for (int j = 0; j < 6; j++) s += fc1w[t * 6 + j] * m[j];
        a1[t] = fmaxf(s, 0.0f);
    }
    __syncthreads();
    if (t < 6) {
        float s = fc2b[t];
        for (int i = 0; i < 30; i++) s += fc2w[t * 30 + i] * a1[i];
        float att = 1.0f / (1.0f + expf(-s));
        // XM >= 0 (post-relu) and att > 0  =>  relu(att*XM) = att*XM
        g_coef[t] = att * convw[t];
    }
}

// out[n,d] = sum_c coef[c] * flat[c*CHUNK + d*N + n] + conv_b
__global__ void k_final(float* __restrict__ out, const float* __restrict__ convb) {
    __shared__ float tile[64][65];
    int t = threadIdx.x;
    int n0 = blockIdx.x * 64;
    int tx = t & 63;
    int ty = t >> 6;  // 0..3
    int n = n0 + tx;
    float cb = convb[0];
    float acc[16];
#pragma unroll
    for (int k = 0; k < 16; k++) acc[k] = cb;
    if (n < NN) {
#pragma unroll
        for (int c = 0; c < 6; c++) {
            float cf = g_coef[c];
            size_t base = (size_t)c * CHUNK + n;
#pragma unroll
            for (int k = 0; k < 16; k++) {
                int d = ty * 16 + k;
                acc[k] += cf * g_XM[base + (size_t)d * NN];
            }
        }
    }
#pragma unroll
    for (int k = 0; k < 16; k++) tile[tx][ty * 16 + k] = acc[k];
    __syncthreads();
    for (int i = t; i < 4096; i += 256) {
        int r = i >> 6, d = i & 63;
        int nn2 = n0 + r;
        if (nn2 < NN) out[(size_t)nn2 * DD + d] = tile[r][d];
    }
}

// ---------------- launcher ----------------
extern "C" void kernel_launch(void* const* d_in, const int* in_sizes, int n_in,
                              void* d_out, int out_size) {
    const float *x, *wg[3], *W1, *b1, *W2, *b2, *fc1w, *fc1b, *fc2w, *fc2b, *convw, *convb;
    const int* eg[3];
    if (in_sizes[4] == 4096) {
        // reference-signature order
        x = (const float*)d_in[0];
        wg[0] = (const float*)d_in[1]; wg[1] = (const float*)d_in[2]; wg[2] = (const float*)d_in[3];
        W1 = (const float*)d_in[4];  b1 = (const float*)d_in[5];
        W2 = (const float*)d_in[6];  b2 = (const float*)d_in[7];
        fc1w = (const float*)d_in[8];  fc1b = (const float*)d_in[9];
        fc2w = (const float*)d_in[10]; fc2b = (const float*)d_in[11];
        convw = (const float*)d_in[12]; convb = (const float*)d_in[13];
        eg[0] = (const int*)d_in[14]; eg[1] = (const int*)d_in[15]; eg[2] = (const int*)d_in[16];
    } else {
        // setup_inputs dict order
        x = (const float*)d_in[0];
        wg[0] = (const float*)d_in[1]; wg[1] = (const float*)d_in[2]; wg[2] = (const float*)d_in[3];
        eg[0] = (const int*)d_in[4]; eg[1] = (const int*)d_in[5]; eg[2] = (const int*)d_in[6];
        W1 = (const float*)d_in[7];  b1 = (const float*)d_in[8];
        W2 = (const float*)d_in[9];  b2 = (const float*)d_in[10];
        fc1w = (const float*)d_in[11]; fc1b = (const float*)d_in[12];
        fc2w = (const float*)d_in[13]; fc2b = (const float*)d_in[14];
        convw = (const float*)d_in[15]; convb = (const float*)d_in[16];
    }
    float* out = (float*)d_out;

    float *h1p, *h2p, *xmp;
    cudaGetSymbolAddress((void**)&h1p, g_h1);
    cudaGetSymbolAddress((void**)&h2p, g_h2);
    cudaGetSymbolAddress((void**)&xmp, g_XM);

    const int EB = (EE + 255) / 256;        // 12500
    const int NB1 = (NN + 255) / 256;       // 391
    const int WB = (NN * 32 + 255) / 256;   // 12500 (warp per node)
    const int GB = (NN + 63) / 64;          // 1563

    // h1 = x @ W1 (shared by all three graphs)
    k_gemm<<<GB, 256>>>(x, DD, W1, h1p);

    for (int G = 0; G < 3; G++) {
        const int* row = eg[G];
        const int* colp = eg[G] + EE;
        const float* w = wg[G];
        k_zero_graph<<<NB1, 256>>>();
        k_deg_hist<<<EB, 256>>>(colp, w);
        k_dinv<<<NB1, 256>>>();
        k_scan<<<1, 1024>>>();
        k_scatter<<<EB, 256>>>(row, colp, w);
        // layer 1: g1 = relu(agg(h1) + b1) -> XM block 2G
        k_aggregate<<<WB, 256>>>(h1p, b1, xmp + 2 * G * DD);
        // h2 = g1 @ W2
        k_gemm<<<GB, 256>>>(xmp + 2 * G * DD, NBCOLS, W2, h2p);
        // layer 2: g2 = relu(agg(h2) + b2) -> XM block 2G+1
        k_aggregate<<<WB, 256>>>(h2p, b2, xmp + (2 * G + 1) * DD);
    }

    k_zero8<<<1, 32>>>();
    k_chunksum<<<dim3(264, 6), 256>>>();
    k_att<<<1, 32>>>(fc1w, fc1b, fc2w, fc2b, convw);
    k_final<<<GB, 256>>>(out, convb);
}

// round 3
// speedup vs baseline: 1.4440x; 1.4440x over previous
#include <cuda_runtime.h>
#include <math.h>

#define NN 100000
#define EE 3200000
#define DD 64
#define NBCOLS 384
#define CHUNK 6400000
#define NBLK 391   // ceil(NN/256)

// ---------------- static device scratch ----------------
__device__ float g_XM[(size_t)NN * NBCOLS];       // [N, 6*D] (153.6 MB)
__device__ float g_h1[(size_t)NN * DD];           // x @ W1
__device__ float g_h2[3][(size_t)NN * DD];        // per-graph layer-2 h
__device__ float g_deg[3][NN];
__device__ float g_dinv[3][NN];
__device__ int   g_cnt[3][NN + 1];                // histogram -> col_ptr
__device__ int   g_cursor[3][NN];
__device__ int2  g_csc[3][EE];                    // {src, norm bits}
__device__ int   g_bsum[3][NBLK + 1];
__device__ float g_csum[8];
__device__ float g_coef[8];

// ---------------- zero everything per launch ----------------
__global__ void k_zero() {
    int i = blockIdx.x * blockDim.x + threadIdx.x;
    if (i < 3 * NN) {
        ((float*)g_deg)[i] = 0.0f;
        int g = i / NN, n = i - g * NN;
        g_cnt[g][n] = 0;
    }
    if (i < 8) g_csum[i] = 0.0f;
}

// ---------------- batched histogram (3 graphs) ----------------
__global__ void k_deg_hist(const int* __restrict__ e0, const int* __restrict__ e1,
                           const int* __restrict__ e2, const float* __restrict__ w0,
                           const float* __restrict__ w1, const float* __restrict__ w2) {
    int g = blockIdx.y;
    const int* col = (g == 0 ? e0 : g == 1 ? e1 : e2) + EE;
    const float* w = (g == 0 ? w0 : g == 1 ? w1 : w2);
    int e = blockIdx.x * blockDim.x + threadIdx.x;
    if (e >= EE) return;
    int c = col[e];
    atomicAdd(&g_deg[g][c], w[e]);
    atomicAdd(&g_cnt[g][c], 1);
}

__global__ void k_dinv() {
    int i = blockIdx.x * blockDim.x + threadIdx.x;
    if (i < 3 * NN) ((float*)g_dinv)[i] = rsqrtf(((float*)g_deg)[i] + 1.0f);
}

// ---------------- 3-phase scan ----------------
__global__ void k_scan1() {   // block sums
    int g = blockIdx.y, b = blockIdx.x, t = threadIdx.x;
    int i = b * 256 + t;
    int v = (i < NN) ? g_cnt[g][i] : 0;
    __shared__ int sh[256];
    sh[t] = v;
    __syncthreads();
    for (int o = 128; o; o >>= 1) { if (t < o) sh[t] += sh[t + o]; __syncthreads(); }
    if (t == 0) g_bsum[g][b] = sh[0];
}

__global__ void k_scan2() {   // per-graph scan of NBLK block sums (1 block/graph)
    int g = blockIdx.x, t = threadIdx.x;       // 512 threads
    __shared__ int sh[512];
    int v = (t < NBLK) ? g_bsum[g][t] : 0;
    sh[t] = v;
    __syncthreads();
    for (int o = 1; o < 512; o <<= 1) {
        int u = (t >= o) ? sh[t - o] : 0;
        __syncthreads();
        sh[t] += u;
        __syncthreads();
    }
    if (t < NBLK) g_bsum[g][t] = sh[t] - v;    // exclusive
}

__global__ void k_scan3() {   // block-local exclusive scan + offset -> col_ptr, cursor
    int g = blockIdx.y, b = blockIdx.x, t = threadIdx.x;
    int i = b * 256 + t;
    int v = (i < NN) ? g_cnt[g][i] : 0;
    __shared__ int sh[256];
    sh[t] = v;
    __syncthreads();
    for (int o = 1; o < 256; o <<= 1) {
        int u = (t >= o) ? sh[t - o] : 0;
        __syncthreads();
        sh[t] += u;
        __syncthreads();
    }
    if (i < NN) {
        int p = g_bsum[g][b] + sh[t] - v;
        g_cnt[g][i] = p;
        g_cursor[g][i] = p;
    }
    if (b == NBLK - 1 && t == 255) g_cnt[g][NN] = EE;
}

__global__ void k_scatter(const int* __restrict__ e0, const int* __restrict__ e1,
                          const int* __restrict__ e2, const float* __restrict__ w0,
                          const float* __restrict__ w1, const float* __restrict__ w2) {
    int g = blockIdx.y;
    const int* ei = (g == 0 ? e0 : g == 1 ? e1 : e2);
    const float* w = (g == 0 ? w0 : g == 1 ? w1 : w2);
    int e = blockIdx.x * blockDim.x + threadIdx.x;
    if (e >= EE) return;
    int r = ei[e];
    int c = ei[EE + e];
    int slot = atomicAdd(&g_cursor[g][c], 1);
    float nrm = g_dinv[g][r] * w[e] * g_dinv[g][c];
    g_csc[g][slot] = make_int2(r, __float_as_int(nrm));
}

// ---------------- GEMMs ----------------
__device__ __forceinline__ void gemm_tile(const float* __restrict__ A, int lda,
                                          const float* __restrict__ Wm,
                                          float* __restrict__ H, int n0) {
    __shared__ float sA[64][65];
    __shared__ float sW[64 * 64];
    int t = threadIdx.x;
    for (int i = t; i < 4096; i += 256) sW[i] = Wm[i];
    for (int i = t; i < 4096; i += 256) {
        int r = i >> 6, c = i & 63;
        int n = n0 + r;
        sA[r][c] = (n < NN) ? A[(size_t)n * lda + c] : 0.0f;
    }
    __syncthreads();
    int d2 = t & 31;
    int rg = t >> 5;
    float2 acc[8];
#pragma unroll
    for (int i = 0; i < 8; i++) acc[i] = make_float2(0.f, 0.f);
    const float2* sW2 = (const float2*)sW;
#pragma unroll 8
    for (int k = 0; k < 64; k++) {
        float2 wv = sW2[k * 32 + d2];
#pragma unroll
        for (int i = 0; i < 8; i++) {
            float a = sA[rg * 8 + i][k];
            acc[i].x += a * wv.x;
            acc[i].y += a * wv.y;
        }
    }
#pragma unroll
    for (int i = 0; i < 8; i++) {
        int n = n0 + rg * 8 + i;
        if (n < NN) *(float2*)&H[(size_t)n * DD + 2 * d2] = acc[i];
    }
}

__global__ void __launch_bounds__(256) k_gemm1(const float* __restrict__ A,
                                               const float* __restrict__ Wm) {
    gemm_tile(A, DD, Wm, g_h1, blockIdx.x * 64);
}

__global__ void __launch_bounds__(256) k_gemm2(const float* __restrict__ Wm) {
    int G = blockIdx.y;
    gemm_tile(g_XM + 2 * G * DD, NBCOLS, Wm, g_h2[G], blockIdx.x * 64);
}

// ---------------- batched aggregate (+fused chunk sums) ----------------
__global__ void __launch_bounds__(256) k_agg(const float* __restrict__ Hbase,
                                             int perGraphH, int layer,
                                             const float* __restrict__ bias) {
    int G = blockIdx.y;
    const float* H = Hbase + (size_t)G * perGraphH;
    int w = threadIdx.x >> 5;
    int lane = threadIdx.x & 31;
    int node = blockIdx.x * 8 + w;      // NN == 12500*8, always valid
    int blk = 2 * G + layer;
    const int* cp = g_cnt[G];
    const int2* csc = g_csc[G];
    int beg = cp[node];
    int end = cp[node + 1];
    float dj = g_dinv[G][node];
    float sl = dj * dj;
    float2 acc = *(const float2*)&H[(size_t)node * DD + 2 * lane];
    acc.x *= sl; acc.y *= sl;
    int e = beg;
    // 4-edge unroll with 8B-aligned int2 loads (csc[e] only guaranteed 8B aligned)
    for (; e + 4 <= end; e += 4) {
        int2 p0 = csc[e];
        int2 p1 = csc[e + 1];
        int2 p2 = csc[e + 2];
        int2 p3 = csc[e + 3];
        float2 h0 = *(const float2*)&H[(size_t)p0.x * DD + 2 * lane];
        float2 h1 = *(const float2*)&H[(size_t)p1.x * DD + 2 * lane];
        float2 h2 = *(const float2*)&H[(size_t)p2.x * DD + 2 * lane];
        float2 h3 = *(const float2*)&H[(size_t)p3.x * DD + 2 * lane];
        float n0 = __int_as_float(p0.y), n1 = __int_as_float(p1.y);
        float n2 = __int_as_float(p2.y), n3 = __int_as_float(p3.y);
        acc.x += n0 * h0.x; acc.y += n0 * h0.y;
        acc.x += n1 * h1.x; acc.y += n1 * h1.y;
        acc.x += n2 * h2.x; acc.y += n2 * h2.y;
        acc.x += n3 * h3.x; acc.y += n3 * h3.y;
    }
    for (; e < end; e++) {
        int2 p = csc[e];
        float2 h0 = *(const float2*)&H[(size_t)p.x * DD + 2 * lane];
        float n0 = __int_as_float(p.y);
        acc.x += n0 * h0.x; acc.y += n0 * h0.y;
    }
    float2 bv = *(const float2*)&bias[2 * lane];
    acc.x = fmaxf(acc.x + bv.x, 0.0f);
    acc.y = fmaxf(acc.y + bv.y, 0.0f);
    *(float2*)&g_XM[(size_t)node * NBCOLS + blk * DD + 2 * lane] = acc;

    // fused chunk-sum: all 64 outputs of this warp land in chunk (6*node+blk)/100000
    float s = acc.x + acc.y;
#pragma unroll
    for (int o = 16; o; o >>= 1) s += __shfl_down_sync(0xffffffffu, s, o);
    __shared__ float ws[8];
    __shared__ int wc[8];
    if (lane == 0) { ws[w] = s; wc[w] = (node * 6 + blk) / 100000; }
    __syncthreads();
    if (threadIdx.x == 0) {
        int c0 = wc[0], c1 = -1;
        float s0 = 0.f, s1v = 0.f;
#pragma unroll
        for (int i = 0; i < 8; i++) {
            if (wc[i] == c0) s0 += ws[i];
            else { c1 = wc[i]; s1v += ws[i]; }
        }
        atomicAdd(&g_csum[c0], s0);
        if (c1 >= 0) atomicAdd(&g_csum[c1], s1v);
    }
}

// ---------------- epilogue ----------------
__global__ void k_att(const float* __restrict__ fc1w, const float* __restrict__ fc1b,
                      const float* __restrict__ fc2w, const float* __restrict__ fc2b,
                      const float* __restrict__ convw) {
    __shared__ float m[6], a1[30];
    int t = threadIdx.x;
    if (t < 6) m[t] = g_csum[t] * (1.0f / (float)CHUNK);
    __syncthreads();
    if (t < 30) {
        float s = fc1b[t];
        for (int j = 0; j < 6; j++) s += fc1w[t * 6 + j] * m[j];
        a1[t] = fmaxf(s, 0.0f);
    }
    __syncthreads();
    if (t < 6) {
        float s = fc2b[t];
        for (int i = 0; i < 30; i++) s += fc2w[t * 30 + i] * a1[i];
        float att = 1.0f / (1.0f + expf(-s));
        g_coef[t] = att * convw[t];   // relu(att*XM)=att*XM since XM>=0, att>0
    }
}

// out[n,d] = sum_c coef[c] * flat[c*CHUNK + d*N + n] + conv_b
__global__ void __launch_bounds__(256) k_final(float* __restrict__ out,
                                               const float* __restrict__ convb) {
    __shared__ float tile[64][65];
    int t = threadIdx.x;
    int n0 = blockIdx.x * 64;
    int tx = t & 63;
    int ty = t >> 6;
    int n = n0 + tx;
    float cb = convb[0];
    float acc[16];
#pragma unroll
    for (int k = 0; k < 16; k++) acc[k] = cb;
    if (n < NN) {
#pragma unroll
        for (int c = 0; c < 6; c++) {
            float cf = g_coef[c];
            size_t base = (size_t)c * CHUNK + n;
#pragma unroll
            for (int k = 0; k < 16; k++) {
                int d = ty * 16 + k;
                acc[k] += cf * g_XM[base + (size_t)d * NN];
            }
        }
    }
#pragma unroll
    for (int k = 0; k < 16; k++) tile[tx][ty * 16 + k] = acc[k];
    __syncthreads();
    for (int i = t; i < 4096; i += 256) {
        int r = i >> 6, d = i & 63;
        int nn2 = n0 + r;
        if (nn2 < NN) out[(size_t)nn2 * DD + d] = tile[r][d];
    }
}

// ---------------- launcher ----------------
extern "C" void kernel_launch(void* const* d_in, const int* in_sizes, int n_in,
                              void* d_out, int out_size) {
    const float *x, *wg[3], *W1, *b1, *W2, *b2, *fc1w, *fc1b, *fc2w, *fc2b, *convw, *convb;
    const int* eg[3];
    if (in_sizes[4] == 4096) {
        x = (const float*)d_in[0];
        wg[0] = (const float*)d_in[1]; wg[1] = (const float*)d_in[2]; wg[2] = (const float*)d_in[3];
        W1 = (const float*)d_in[4];  b1 = (const float*)d_in[5];
        W2 = (const float*)d_in[6];  b2 = (const float*)d_in[7];
        fc1w = (const float*)d_in[8];  fc1b = (const float*)d_in[9];
        fc2w = (const float*)d_in[10]; fc2b = (const float*)d_in[11];
        convw = (const float*)d_in[12]; convb = (const float*)d_in[13];
        eg[0] = (const int*)d_in[14]; eg[1] = (const int*)d_in[15]; eg[2] = (const int*)d_in[16];
    } else {
        x = (const float*)d_in[0];
        wg[0] = (const float*)d_in[1]; wg[1] = (const float*)d_in[2]; wg[2] = (const float*)d_in[3];
        eg[0] = (const int*)d_in[4]; eg[1] = (const int*)d_in[5]; eg[2] = (const int*)d_in[6];
        W1 = (const float*)d_in[7];  b1 = (const float*)d_in[8];
        W2 = (const float*)d_in[9];  b2 = (const float*)d_in[10];
        fc1w = (const float*)d_in[11]; fc1b = (const float*)d_in[12];
        fc2w = (const float*)d_in[13]; fc2b = (const float*)d_in[14];
        convw = (const float*)d_in[15]; convb = (const float*)d_in[16];
    }
    float* out = (float*)d_out;

    float *h1p;
    cudaGetSymbolAddress((void**)&h1p, g_h1);
    float *h2p;
    cudaGetSymbolAddress((void**)&h2p, g_h2);

    const int EB = (EE + 255) / 256;          // 12500
    const int ZB = (3 * NN + 255) / 256;      // 1172
    const int AB = NN / 8;                    // 12500 (8 warps/block, 1 node/warp)
    const int GB = (NN + 63) / 64;            // 1563

    // h1 = x @ W1
    k_gemm1<<<GB, 256>>>(x, W1);

    // batched CSC build for all 3 graphs
    k_zero<<<ZB, 256>>>();
    k_deg_hist<<<dim3(EB, 3), 256>>>(eg[0], eg[1], eg[2], wg[0], wg[1], wg[2]);
    k_dinv<<<ZB, 256>>>();
    k_scan1<<<dim3(NBLK, 3), 256>>>();
    k_scan2<<<3, 512>>>();
    k_scan3<<<dim3(NBLK, 3), 256>>>();
    k_scatter<<<dim3(EB, 3), 256>>>(eg[0], eg[1], eg[2], wg[0], wg[1], wg[2]);

    // layer 1 (all graphs), layer-2 GEMM (all graphs), layer 2 (all graphs)
    k_agg<<<dim3(AB, 3), 256>>>(h1p, 0, 0, b1);
    k_gemm2<<<dim3(GB, 3), 256>>>(W2);
    k_agg<<<dim3(AB, 3), 256>>>(h2p, NN * DD, 1, b2);

    k_att<<<1, 32>>>(fc1w, fc1b, fc2w, fc2b, convw);
    k_final<<<GB, 256>>>(out, convb);
}